// round 15
// baseline (speedup 1.0000x reference)
#include <cuda_runtime.h>
#include <cstdint>
#include <math.h>

// ---------------- problem constants ----------------
#define FDIM 221
#define BATCH 2048
#define XS 224
#define NPAD 256
#define DDIM 13
#define SDIM 26
#define EDIM 8
#define VDIM 100000
#define TRI 24531             // F*(F+1)/2 valid triangle rows
#define TRIP2 24544           // padded K, multiple of 32
#define BKC 32
#define CHUNKS (TRIP2 / BKC)  // 767
#define KSPLIT 9
#define CPS 86                // ceil(767/9)
#define BM 64
#define NTHREADS 288          // 8 consumer warps + 1 producer warp
#define NCONS 256

// ---------------- gemm smem layout (dynamic) ----------------
#define W_STG (BKC * NPAD * 4)          // 32768 B
#define A_STG (BKC * BM * 8)            // 16384 B (duplicated f32x2 pairs)
#define OFF_W0 0
#define OFF_W1 W_STG
#define OFF_A0 (2 * W_STG)
#define OFF_A1 (2 * W_STG + A_STG)
#define SMEM_GEMM (2 * W_STG + 2 * A_STG)   // 98304 B

// ---------------- scratch (device globals; no allocation APIs) ----------------
__device__ float d_X1T[FDIM * BATCH];                  // transposed x: [feature][batch]
__device__ float d_X2[BATCH * XS];
__device__ float d_Wp1[(size_t)TRIP2 * NPAD];          // 25.1 MB folded W1
__device__ float d_Yp[(size_t)KSPLIT * BATCH * NPAD];  // 18.9 MB split-K partials
__device__ float d_w2t[TRIP2];                         // folded column-sums of W2
__device__ float d_b2s;
__device__ __align__(16) int d_Tij[TRIP2];             // i | (j<<16)

// ---------------- helpers ----------------
__device__ __forceinline__ uint32_t smem_u32(const void* p) {
    uint32_t a;
    asm("{ .reg .u64 t; cvta.to.shared.u64 t, %1; cvt.u32.u64 %0, t; }" : "=r"(a) : "l"(p));
    return a;
}
__device__ __forceinline__ void cpa16(uint32_t sm, const void* g) {
    asm volatile("cp.async.cg.shared.global [%0], [%1], 16;" :: "r"(sm), "l"(g));
}
__device__ __forceinline__ void fma2(unsigned long long& acc,
                                     unsigned long long a,
                                     unsigned long long b) {
    asm("fma.rn.f32x2 %0, %1, %2, %0;" : "+l"(acc) : "l"(a), "l"(b));
}
__device__ __forceinline__ float2 unpack2f(unsigned long long v) {
    float2 f;
    asm("mov.b64 {%0, %1}, %2;" : "=f"(f.x), "=f"(f.y) : "l"(v));
    return f;
}
__device__ __forceinline__ void mbar_init(uint32_t a, uint32_t c) {
    asm volatile("mbarrier.init.shared.b64 [%0], %1;" :: "r"(a), "r"(c) : "memory");
}
__device__ __forceinline__ void mbar_arrive(uint32_t a) {
    asm volatile("mbarrier.arrive.shared.b64 _, [%0];" :: "r"(a) : "memory");
}
__device__ __forceinline__ void mbar_cp_arrive(uint32_t a) {
    asm volatile("cp.async.mbarrier.arrive.shared::cta.b64 [%0];" :: "r"(a) : "memory");
}
__device__ __forceinline__ void mbar_wait(uint32_t a, uint32_t ph) {
    asm volatile(
        "{\n\t.reg .pred P;\n\t"
        "W_%=:\n\t"
        "mbarrier.try_wait.parity.acquire.cta.shared::cta.b64 P, [%0], %1, 0x989680;\n\t"
        "@P bra.uni D_%=;\n\t"
        "bra.uni W_%=;\n\t"
        "D_%=:\n\t}"
        :: "r"(a), "r"(ph) : "memory");
}

// ---------------- 1) packed triangle index table ----------------
__global__ void make_pairs_kernel() {
    int tid = threadIdx.x;
    for (int i = tid; i < FDIM; i += blockDim.x) {
        int start = i * FDIM - (i * (i - 1)) / 2;
        for (int j = i; j < FDIM; j++)
            d_Tij[start + j - i] = i | (j << 16);
    }
    for (int r = TRI + tid; r < TRIP2; r += blockDim.x) d_Tij[r] = 0;
}

// ---------------- 2) fold W1 -> Wp1[TRIP2][256] ----------------
__global__ void pack1_kernel(const float* __restrict__ W) {
    int r = blockIdx.x;
    float* dst = d_Wp1 + (size_t)r * NPAD;
    if (r >= TRI) {
        for (int c = threadIdx.x; c < NPAD; c += blockDim.x) dst[c] = 0.f;
        return;
    }
    int p = d_Tij[r];
    int i = p & 0xffff, j = p >> 16;
    const float* wa = W + ((size_t)i * FDIM + j) * FDIM;
    const float* wb = W + ((size_t)j * FDIM + i) * FDIM;
    for (int c = threadIdx.x; c < NPAD; c += blockDim.x) {
        float v = 0.f;
        if (c < FDIM) {
            v = wa[c];
            if (i != j) v += wb[c];
        }
        dst[c] = v;
    }
}

// ---------------- 3) fold column-sums of W2 -> w2t (layer 2 collapses to a quadratic form) ----------------
__global__ void w2sum_kernel(const float* __restrict__ W2) {
    int r = blockIdx.x * 8 + (threadIdx.x >> 5);
    int lane = threadIdx.x & 31;
    if (r >= TRIP2) return;
    float s = 0.f;
    if (r < TRI) {
        int p = d_Tij[r];
        int i = p & 0xffff, j = p >> 16;
        const float* wa = W2 + ((size_t)i * FDIM + j) * FDIM;
        const float* wb = W2 + ((size_t)j * FDIM + i) * FDIM;
        for (int f = lane; f < FDIM; f += 32) {
            s += wa[f];
            if (i != j) s += wb[f];
        }
    }
#pragma unroll
    for (int o = 16; o > 0; o >>= 1) s += __shfl_down_sync(0xffffffffu, s, o);
    if (lane == 0) d_w2t[r] = s;
}
__global__ void b2sum_kernel(const float* __restrict__ b2) {
    __shared__ float red[8];
    int lane = threadIdx.x & 31, warp = threadIdx.x >> 5;
    float s = 0.f;
    for (int f = threadIdx.x; f < FDIM; f += 256) s += b2[f];
#pragma unroll
    for (int o = 16; o > 0; o >>= 1) s += __shfl_down_sync(0xffffffffu, s, o);
    if (lane == 0) red[warp] = s;
    __syncthreads();
    if (threadIdx.x == 0) {
        float t = 0.f;
#pragma unroll
        for (int w = 0; w < 8; w++) t += red[w];
        d_b2s = t;
    }
}

// ---------------- 4) build x transposed: X1T[feature][batch] ----------------
__global__ void build_x_kernel(const float* __restrict__ dense,
                               const int* __restrict__ sparse,
                               const float* __restrict__ emb) {
    int b = blockIdx.x;
    int t = threadIdx.x;
    if (t >= FDIM) return;
    float v;
    if (t < DDIM) {
        v = dense[b * DDIM + t];
    } else {
        int q = t - DDIM;
        int s = q >> 3;
        int e = q & 7;
        int idx = sparse[b * SDIM + s];
        v = emb[((size_t)s * VDIM + idx) * EDIM + e];
    }
    d_X1T[t * BATCH + b] = v;
}

// ---------------- 5) layer-1 interaction GEMM: warp-specialized, producer-duplicated A ----------------
// Producer (warp 8): W cp.async + A products stored as duplicated f32x2 pairs.
// Consumers (warps 0-7): pure 4xLDS.128(A) + 2xLDS.128(W) + 32 FFMA2 per kk — zero movs.
__global__ void __launch_bounds__(NTHREADS, 2) gemm1_kernel() {
    extern __shared__ __align__(16) char smem[];
    __shared__ __align__(8) unsigned long long mb[4];   // full0, full1, empty0, empty1
    const uint32_t sb = smem_u32(smem);
    const uint32_t mbb = smem_u32(mb);
    const uint32_t fullA[2] = {mbb, mbb + 8};
    const uint32_t emptyA[2] = {mbb + 16, mbb + 24};

    const int tid = threadIdx.x;
    const int mBase = blockIdx.x * BM;
    const int split = blockIdx.y;
    const int c0 = split * CPS;
    const int c1 = min(c0 + CPS, CHUNKS);

    if (tid == 0) {
        mbar_init(fullA[0], 32);   // 32 explicit STS arrivals (cp-arrives are self-balancing)
        mbar_init(fullA[1], 32);
        mbar_init(emptyA[0], NCONS);
        mbar_init(emptyA[1], NCONS);
    }
    __syncthreads();

    if (tid >= NCONS) {
        // ---------------- producer warp ----------------
        const int pl = tid - NCONS;            // 0..31
        const float* xT0 = d_X1T + mBase + pl;
        const float* xT1 = xT0 + 32;
        int s = 0, pe = 1;                     // fresh barriers: empty-wait passes at parity 1
        for (int ch = c0; ch < c1; ch++) {
            mbar_wait(emptyA[s], (uint32_t)pe);
            // W fill: 2048 x 16B over 32 lanes
            const char* wg = (const char*)d_Wp1 + (size_t)ch * W_STG;
            const uint32_t wsm = sb + (s ? OFF_W1 : OFF_W0);
#pragma unroll
            for (int q = 0; q < 64; q++) {
                const int off = (pl + 32 * q) * 16;
                cpa16(wsm + off, wg + off);
            }
            mbar_cp_arrive(fullA[s]);          // +1 expected now, +1 arrival when copies land
            // A build: 2 m-rows per lane, 32 kk products, stored as duplicated pairs
            float2* Asm = (float2*)(smem + (s ? OFF_A1 : OFF_A0));
            const int rb0 = ch * BKC;
#pragma unroll
            for (int g = 0; g < 4; g++) {
                const int4* t4 = (const int4*)(d_Tij + rb0 + g * 8);
                int4 q0 = __ldg(t4);
                int4 q1 = __ldg(t4 + 1);
                int tj[8] = {q0.x, q0.y, q0.z, q0.w, q1.x, q1.y, q1.z, q1.w};
#pragma unroll
                for (int u = 0; u < 8; u++) {
                    const int i = tj[u] & 0xffff, j = tj[u] >> 16;
                    const float v0 = __ldg(xT0 + (size_t)i * BATCH) * __ldg(xT0 + (size_t)j * BATCH);
                    const float v1 = __ldg(xT1 + (size_t)i * BATCH) * __ldg(xT1 + (size_t)j * BATCH);
                    Asm[(g * 8 + u) * BM + pl] = make_float2(v0, v0);
                    Asm[(g * 8 + u) * BM + pl + 32] = make_float2(v1, v1);
                }
            }
            mbar_arrive(fullA[s]);             // release: publishes STS
            s ^= 1;
            if (s == 0) pe ^= 1;
        }
        return;
    }

    // ---------------- consumer warps (tid < 256): mov-free FFMA2 loop ----------------
    const int lane = tid & 31;
    const int wid = tid >> 5;
    const int ml = lane & 3;
    const int nl = lane >> 2;
    const int warpM = wid & 1;
    const int warpN = wid >> 1;

    unsigned long long acc[8][4];  // [g=2q+p: m = 8q+2ml+p][pair s]
#pragma unroll
    for (int a = 0; a < 8; a++)
#pragma unroll
        for (int s2 = 0; s2 < 4; s2++) acc[a][s2] = 0ULL;

    const int wLaneOff = (warpN * 64 + nl * 4) * 4;   // bytes into each W row
    const int aLaneOff = warpM * 256 + ml * 16;       // bytes into each 512B A row (dup pairs)

    int s = 0, pf = 0;
    for (int ch = c0; ch < c1; ch++) {
        mbar_wait(fullA[s], (uint32_t)pf);
        const char* Wb = smem + (s ? OFF_W1 : OFF_W0) + wLaneOff;
        const char* Ab = smem + (s ? OFF_A1 : OFF_A0) + aLaneOff;
#pragma unroll 8
        for (int kk = 0; kk < BKC; kk++) {
            const char* Arow = Ab + kk * (BM * 8);
            const char* Wrow = Wb + kk * (NPAD * 4);
            // A: 4 x LDS.128 of duplicated pairs (no movs)
            ulonglong2 av0 = *reinterpret_cast<const ulonglong2*>(Arow);
            ulonglong2 av1 = *reinterpret_cast<const ulonglong2*>(Arow + 64);
            ulonglong2 av2 = *reinterpret_cast<const ulonglong2*>(Arow + 128);
            ulonglong2 av3 = *reinterpret_cast<const ulonglong2*>(Arow + 192);
            unsigned long long ad[8] = {av0.x, av0.y, av1.x, av1.y,
                                        av2.x, av2.y, av3.x, av3.y};
            // W: natural f32 pairs, 2 x LDS.128
            ulonglong2 w0 = *reinterpret_cast<const ulonglong2*>(Wrow);
            ulonglong2 w1 = *reinterpret_cast<const ulonglong2*>(Wrow + 128);
            unsigned long long wv[4] = {w0.x, w0.y, w1.x, w1.y};
#pragma unroll
            for (int g = 0; g < 8; g++)
#pragma unroll
                for (int s2 = 0; s2 < 4; s2++)
                    fma2(acc[g][s2], ad[g], wv[s2]);
        }
        mbar_arrive(emptyA[s]);                // release stage back to producer
        s ^= 1;
        if (s == 0) pf ^= 1;
    }

    // epilogue: deterministic split-K partial store (STG.128, lanes nl-consecutive)
#pragma unroll
    for (int g = 0; g < 8; g++) {
        const int q = g >> 1, p = g & 1;
        const int m = mBase + warpM * 32 + 8 * q + 2 * ml + p;
        float* dst = d_Yp + ((size_t)split * BATCH + m) * NPAD + warpN * 64 + nl * 4;
#pragma unroll
        for (int h = 0; h < 2; h++) {
            float2 lo = unpack2f(acc[g][h * 2]);
            float2 hi = unpack2f(acc[g][h * 2 + 1]);
            *reinterpret_cast<float4*>(dst + h * 32) = make_float4(lo.x, lo.y, hi.x, hi.y);
        }
    }
}

// ---------------- 6) reduce split-K partials + bias -> X2 (zero-padded to 224) ----------------
__global__ void reduce1_kernel(const float* __restrict__ b1) {
    int m = blockIdx.x;
    int c = threadIdx.x;
    float v = 0.f;
    if (c < FDIM) {
        v = b1[c];
#pragma unroll
        for (int p = 0; p < KSPLIT; p++)
            v += d_Yp[((size_t)p * BATCH + m) * NPAD + c];
    }
    d_X2[m * XS + c] = v;
}

// ---------------- 7) final: pooled = x2^T S2 x2 + sum(b2); sigmoid ----------------
#define RPB 4
__global__ void final_kernel(const float* __restrict__ out_w,
                             const float* __restrict__ out_b,
                             float* __restrict__ out) {
    __shared__ float xs[RPB][XS];
    __shared__ float red[8][RPB];
    const int tid = threadIdx.x;
    const int b0 = blockIdx.x * RPB;
    for (int idx = tid; idx < RPB * XS; idx += 256)
        xs[idx / XS][idx % XS] = d_X2[(size_t)(b0 + idx / XS) * XS + (idx % XS)];
    __syncthreads();

    float acc[RPB] = {0.f, 0.f, 0.f, 0.f};
    for (int r = tid; r < TRIP2; r += 256) {
        const float w = __ldg(&d_w2t[r]);
        const int p = __ldg(&d_Tij[r]);
        const int i = p & 0xffff, j = p >> 16;
#pragma unroll
        for (int q = 0; q < RPB; q++)
            acc[q] += xs[q][i] * xs[q][j] * w;
    }
    const int lane = tid & 31, warp = tid >> 5;
#pragma unroll
    for (int q = 0; q < RPB; q++) {
        float s = acc[q];
#pragma unroll
        for (int o = 16; o > 0; o >>= 1) s += __shfl_down_sync(0xffffffffu, s, o);
        if (lane == 0) red[warp][q] = s;
    }
    __syncthreads();
    if (tid < RPB) {
        float s = 0.f;
#pragma unroll
        for (int w = 0; w < 8; w++) s += red[w][tid];
        const float pooled = s + d_b2s;
        const float z = pooled * out_w[0] + out_b[0];
        out[b0 + tid] = 1.f / (1.f + expf(-z));
    }
}

extern "C" void kernel_launch(void* const* d_in, const int* in_sizes, int n_in,
                              void* d_out, int out_size) {
    const float* dense = (const float*)d_in[0];
    const int* sparse = (const int*)d_in[1];
    const float* emb = (const float*)d_in[2];
    const float* W1 = (const float*)d_in[3];
    const float* b1 = (const float*)d_in[4];
    const float* W2 = (const float*)d_in[5];
    const float* b2 = (const float*)d_in[6];
    // d_in[7..10]: attention weights — mathematically dead (softmax over size-1 axis == 1)
    const float* out_w = (const float*)d_in[11];
    const float* out_b = (const float*)d_in[12];
    float* out = (float*)d_out;

    cudaFuncSetAttribute(gemm1_kernel, cudaFuncAttributeMaxDynamicSharedMemorySize, SMEM_GEMM);

    // Launch order keeps gemm1 as launch #4 (the one ncu captures).
    make_pairs_kernel<<<1, 256>>>();
    pack1_kernel<<<TRIP2, 64>>>(W1);
    build_x_kernel<<<BATCH, XS>>>(dense, sparse, emb);
    gemm1_kernel<<<dim3(BATCH / BM, KSPLIT), NTHREADS, SMEM_GEMM>>>();
    w2sum_kernel<<<(TRIP2 + 7) / 8, 256>>>(W2);       // independent of gemm1
    b2sum_kernel<<<1, 256>>>(b2);
    reduce1_kernel<<<BATCH, XS>>>(b1);
    final_kernel<<<BATCH / RPB, 256>>>(out_w, out_b, out);
}

// round 16
// speedup vs baseline: 1.2020x; 1.2020x over previous
#include <cuda_runtime.h>
#include <cstdint>
#include <math.h>

// ---------------- problem constants ----------------
#define FDIM 221
#define BATCH 2048
#define XS 224
#define NPAD 256
#define DDIM 13
#define SDIM 26
#define EDIM 8
#define VDIM 100000
#define TRI 24531             // F*(F+1)/2 valid triangle rows
#define TRIP2 24544           // padded K, multiple of 32
#define BKC 32
#define CHUNKS (TRIP2 / BKC)  // 767
#define KSPLIT 9
#define CPS 86                // ceil(767/9)
#define BM 64
#define NTHREADS 288          // 8 consumer warps + 1 producer warp
#define NCONS 256

// ---------------- gemm smem layout (dynamic) ----------------
#define W_STG (BKC * NPAD * 4)          // 32768 B
#define A_STG (BKC * BM * 4)            // 8192 B (plain f32, unduplicated)
#define OFF_W0 0
#define OFF_W1 W_STG
#define OFF_A0 (2 * W_STG)
#define OFF_A1 (2 * W_STG + A_STG)
#define SMEM_GEMM (2 * W_STG + 2 * A_STG)   // 81920 B

// ---------------- scratch (device globals; no allocation APIs) ----------------
__device__ float d_X1T[FDIM * BATCH];                  // transposed x: [feature][batch]
__device__ float d_Wp1[(size_t)TRIP2 * NPAD];          // 25.1 MB folded W1
__device__ float d_Yp[(size_t)KSPLIT * BATCH * NPAD];  // 18.9 MB split-K partials
__device__ float d_w2t[TRIP2];                         // folded column-sums of W2
__device__ float d_b2s;
__device__ __align__(16) int d_Tij[TRIP2];             // i | (j<<16)

// ---------------- helpers ----------------
__device__ __forceinline__ uint32_t smem_u32(const void* p) {
    uint32_t a;
    asm("{ .reg .u64 t; cvta.to.shared.u64 t, %1; cvt.u32.u64 %0, t; }" : "=r"(a) : "l"(p));
    return a;
}
__device__ __forceinline__ void cpa16(uint32_t sm, const void* g) {
    asm volatile("cp.async.cg.shared.global [%0], [%1], 16;" :: "r"(sm), "l"(g));
}
__device__ __forceinline__ void fma2(unsigned long long& acc,
                                     unsigned long long a,
                                     unsigned long long b) {
    asm("fma.rn.f32x2 %0, %1, %2, %0;" : "+l"(acc) : "l"(a), "l"(b));
}
__device__ __forceinline__ unsigned long long pack2f(float x) {
    unsigned long long r;
    asm("mov.b64 %0, {%1, %1};" : "=l"(r) : "f"(x));
    return r;
}
__device__ __forceinline__ float2 unpack2f(unsigned long long v) {
    float2 f;
    asm("mov.b64 {%0, %1}, %2;" : "=f"(f.x), "=f"(f.y) : "l"(v));
    return f;
}
__device__ __forceinline__ void mbar_init(uint32_t a, uint32_t c) {
    asm volatile("mbarrier.init.shared.b64 [%0], %1;" :: "r"(a), "r"(c) : "memory");
}
__device__ __forceinline__ void mbar_arrive(uint32_t a) {
    asm volatile("mbarrier.arrive.shared.b64 _, [%0];" :: "r"(a) : "memory");
}
__device__ __forceinline__ void mbar_cp_arrive(uint32_t a) {
    asm volatile("cp.async.mbarrier.arrive.shared::cta.b64 [%0];" :: "r"(a) : "memory");
}
__device__ __forceinline__ void mbar_wait(uint32_t a, uint32_t ph) {
    asm volatile(
        "{\n\t.reg .pred P;\n\t"
        "W_%=:\n\t"
        "mbarrier.try_wait.parity.acquire.cta.shared::cta.b64 P, [%0], %1, 0x989680;\n\t"
        "@P bra.uni D_%=;\n\t"
        "bra.uni W_%=;\n\t"
        "D_%=:\n\t}"
        :: "r"(a), "r"(ph) : "memory");
}

// ---------------- 1) packed triangle index table ----------------
__global__ void make_pairs_kernel() {
    int tid = threadIdx.x;
    for (int i = tid; i < FDIM; i += blockDim.x) {
        int start = i * FDIM - (i * (i - 1)) / 2;
        for (int j = i; j < FDIM; j++)
            d_Tij[start + j - i] = i | (j << 16);
    }
    for (int r = TRI + tid; r < TRIP2; r += blockDim.x) d_Tij[r] = 0;
}

// ---------------- 2) fold W1 -> Wp1[TRIP2][256] ----------------
__global__ void pack1_kernel(const float* __restrict__ W) {
    int r = blockIdx.x;
    float* dst = d_Wp1 + (size_t)r * NPAD;
    if (r >= TRI) {
        for (int c = threadIdx.x; c < NPAD; c += blockDim.x) dst[c] = 0.f;
        return;
    }
    int p = d_Tij[r];
    int i = p & 0xffff, j = p >> 16;
    const float* wa = W + ((size_t)i * FDIM + j) * FDIM;
    const float* wb = W + ((size_t)j * FDIM + i) * FDIM;
    for (int c = threadIdx.x; c < NPAD; c += blockDim.x) {
        float v = 0.f;
        if (c < FDIM) {
            v = wa[c];
            if (i != j) v += wb[c];
        }
        dst[c] = v;
    }
}

// ---------------- 3) fold column-sums of W2 -> w2t; last block also sums b2 ----------------
#define W2S_BLOCKS ((TRIP2 + 7) / 8)
__global__ void w2sum_kernel(const float* __restrict__ W2, const float* __restrict__ b2) {
    if (blockIdx.x == W2S_BLOCKS) {
        // extra block: Sum(b2) -> d_b2s
        __shared__ float red[8];
        int lane = threadIdx.x & 31, warp = threadIdx.x >> 5;
        float s = 0.f;
        for (int f = threadIdx.x; f < FDIM; f += 256) s += b2[f];
#pragma unroll
        for (int o = 16; o > 0; o >>= 1) s += __shfl_down_sync(0xffffffffu, s, o);
        if (lane == 0) red[warp] = s;
        __syncthreads();
        if (threadIdx.x == 0) {
            float t = 0.f;
#pragma unroll
            for (int w = 0; w < 8; w++) t += red[w];
            d_b2s = t;
        }
        return;
    }
    int r = blockIdx.x * 8 + (threadIdx.x >> 5);
    int lane = threadIdx.x & 31;
    if (r >= TRIP2) return;
    float s = 0.f;
    if (r < TRI) {
        int p = d_Tij[r];
        int i = p & 0xffff, j = p >> 16;
        const float* wa = W2 + ((size_t)i * FDIM + j) * FDIM;
        const float* wb = W2 + ((size_t)j * FDIM + i) * FDIM;
        for (int f = lane; f < FDIM; f += 32) {
            s += wa[f];
            if (i != j) s += wb[f];
        }
    }
#pragma unroll
    for (int o = 16; o > 0; o >>= 1) s += __shfl_down_sync(0xffffffffu, s, o);
    if (lane == 0) d_w2t[r] = s;
}

// ---------------- 4) build x transposed: X1T[feature][batch] ----------------
__global__ void build_x_kernel(const float* __restrict__ dense,
                               const int* __restrict__ sparse,
                               const float* __restrict__ emb) {
    int b = blockIdx.x;
    int t = threadIdx.x;
    if (t >= FDIM) return;
    float v;
    if (t < DDIM) {
        v = dense[b * DDIM + t];
    } else {
        int q = t - DDIM;
        int s = q >> 3;
        int e = q & 7;
        int idx = sparse[b * SDIM + s];
        v = emb[((size_t)s * VDIM + idx) * EDIM + e];
    }
    d_X1T[t * BATCH + b] = v;
}

// ---------------- 5) layer-1 interaction GEMM: warp-specialized producer/consumer (R14) ----------------
__global__ void __launch_bounds__(NTHREADS, 2) gemm1_kernel() {
    extern __shared__ __align__(16) char smem[];
    __shared__ __align__(8) unsigned long long mb[4];   // full0, full1, empty0, empty1
    const uint32_t sb = smem_u32(smem);
    const uint32_t mbb = smem_u32(mb);
    const uint32_t fullA[2] = {mbb, mbb + 8};
    const uint32_t emptyA[2] = {mbb + 16, mbb + 24};

    const int tid = threadIdx.x;
    const int mBase = blockIdx.x * BM;
    const int split = blockIdx.y;
    const int c0 = split * CPS;
    const int c1 = min(c0 + CPS, CHUNKS);

    if (tid == 0) {
        mbar_init(fullA[0], 32);   // 32 explicit STS arrivals (cp-arrives are self-balancing)
        mbar_init(fullA[1], 32);
        mbar_init(emptyA[0], NCONS);
        mbar_init(emptyA[1], NCONS);
    }
    __syncthreads();

    if (tid >= NCONS) {
        // ---------------- producer warp ----------------
        const int pl = tid - NCONS;            // 0..31
        const float* xT0 = d_X1T + mBase + pl;
        const float* xT1 = xT0 + 32;
        int s = 0, pe = 1;                     // fresh barriers: empty-wait passes at parity 1
        for (int ch = c0; ch < c1; ch++) {
            mbar_wait(emptyA[s], (uint32_t)pe);
            // W fill: 2048 x 16B over 32 lanes
            const char* wg = (const char*)d_Wp1 + (size_t)ch * W_STG;
            const uint32_t wsm = sb + (s ? OFF_W1 : OFF_W0);
#pragma unroll
            for (int q = 0; q < 64; q++) {
                const int off = (pl + 32 * q) * 16;
                cpa16(wsm + off, wg + off);
            }
            mbar_cp_arrive(fullA[s]);          // +1 expected now, +1 arrival when copies land
            // A build: 2 m-rows per lane, 32 kk products
            float* Asm = (float*)(smem + (s ? OFF_A1 : OFF_A0));
            const int rb0 = ch * BKC;
#pragma unroll
            for (int g = 0; g < 4; g++) {
                const int4* t4 = (const int4*)(d_Tij + rb0 + g * 8);
                int4 q0 = __ldg(t4);
                int4 q1 = __ldg(t4 + 1);
                int tj[8] = {q0.x, q0.y, q0.z, q0.w, q1.x, q1.y, q1.z, q1.w};
#pragma unroll
                for (int u = 0; u < 8; u++) {
                    const int i = tj[u] & 0xffff, j = tj[u] >> 16;
                    const float v0 = __ldg(xT0 + (size_t)i * BATCH) * __ldg(xT0 + (size_t)j * BATCH);
                    const float v1 = __ldg(xT1 + (size_t)i * BATCH) * __ldg(xT1 + (size_t)j * BATCH);
                    Asm[(g * 8 + u) * BM + pl] = v0;
                    Asm[(g * 8 + u) * BM + pl + 32] = v1;
                }
            }
            mbar_arrive(fullA[s]);             // release: publishes STS
            s ^= 1;
            if (s == 0) pe ^= 1;
        }
        return;
    }

    // ---------------- consumer warps (tid < 256): R12 math loop ----------------
    const int lane = tid & 31;
    const int wid = tid >> 5;
    const int ml = lane & 3;
    const int nl = lane >> 2;
    const int warpM = wid & 1;
    const int warpN = wid >> 1;

    unsigned long long acc[8][4];
#pragma unroll
    for (int a = 0; a < 8; a++)
#pragma unroll
        for (int s2 = 0; s2 < 4; s2++) acc[a][s2] = 0ULL;

    const int wLaneOff = (warpN * 64 + nl * 4) * 4;
    const int aLaneOff = (warpM * 32 + ml * 8) * 4;

    int s = 0, pf = 0;
    for (int ch = c0; ch < c1; ch++) {
        mbar_wait(fullA[s], (uint32_t)pf);
        const char* Wb = smem + (s ? OFF_W1 : OFF_W0) + wLaneOff;
        const char* Ab = smem + (s ? OFF_A1 : OFF_A0) + aLaneOff;
#pragma unroll 8
        for (int kk = 0; kk < BKC; kk++) {
            const char* Arow = Ab + kk * (BM * 4);
            const char* Wrow = Wb + kk * (NPAD * 4);
            float4 a0 = *reinterpret_cast<const float4*>(Arow);
            float4 a1 = *reinterpret_cast<const float4*>(Arow + 16);
            ulonglong2 w0 = *reinterpret_cast<const ulonglong2*>(Wrow);
            ulonglong2 w1 = *reinterpret_cast<const ulonglong2*>(Wrow + 128);
            unsigned long long wv[4] = {w0.x, w0.y, w1.x, w1.y};
            unsigned long long ad[8];
            ad[0] = pack2f(a0.x); ad[1] = pack2f(a0.y);
            ad[2] = pack2f(a0.z); ad[3] = pack2f(a0.w);
            ad[4] = pack2f(a1.x); ad[5] = pack2f(a1.y);
            ad[6] = pack2f(a1.z); ad[7] = pack2f(a1.w);
#pragma unroll
            for (int g = 0; g < 8; g++)
#pragma unroll
                for (int s2 = 0; s2 < 4; s2++)
                    fma2(acc[g][s2], ad[g], wv[s2]);
        }
        mbar_arrive(emptyA[s]);                // release stage back to producer
        s ^= 1;
        if (s == 0) pf ^= 1;
    }

    // epilogue: deterministic split-K partial store (STG.128, lanes nl-consecutive)
#pragma unroll
    for (int g = 0; g < 8; g++) {
        const int m = mBase + warpM * 32 + ml * 8 + g;
        float* dst = d_Yp + ((size_t)split * BATCH + m) * NPAD + warpN * 64 + nl * 4;
#pragma unroll
        for (int h = 0; h < 2; h++) {
            float2 lo = unpack2f(acc[g][h * 2]);
            float2 hi = unpack2f(acc[g][h * 2 + 1]);
            *reinterpret_cast<float4*>(dst + h * 32) = make_float4(lo.x, lo.y, hi.x, hi.y);
        }
    }
}

// ---------------- 6) fused final: reduce split-K + b1 -> x2 row; pooled = x2^T S2 x2 + sum(b2); sigmoid ----------------
#define RPB 4
__global__ void final_kernel(const float* __restrict__ b1,
                             const float* __restrict__ out_w,
                             const float* __restrict__ out_b,
                             float* __restrict__ out) {
    __shared__ float xs[RPB][XS];
    __shared__ float red[8][RPB];
    const int tid = threadIdx.x;
    const int b0 = blockIdx.x * RPB;

    // build x2 rows in smem: same arithmetic order as old reduce1 (b1 first, then p=0..8)
    for (int idx = tid; idx < RPB * XS; idx += 256) {
        const int r = idx / XS;
        const int c = idx % XS;
        float v = 0.f;
        if (c < FDIM) {
            v = b1[c];
#pragma unroll
            for (int p = 0; p < KSPLIT; p++)
                v += d_Yp[((size_t)p * BATCH + (b0 + r)) * NPAD + c];
        }
        xs[r][c] = v;
    }
    __syncthreads();

    float acc[RPB] = {0.f, 0.f, 0.f, 0.f};
    for (int r = tid; r < TRIP2; r += 256) {
        const float w = __ldg(&d_w2t[r]);
        const int p = __ldg(&d_Tij[r]);
        const int i = p & 0xffff, j = p >> 16;
#pragma unroll
        for (int q = 0; q < RPB; q++)
            acc[q] += xs[q][i] * xs[q][j] * w;
    }
    const int lane = tid & 31, warp = tid >> 5;
#pragma unroll
    for (int q = 0; q < RPB; q++) {
        float s = acc[q];
#pragma unroll
        for (int o = 16; o > 0; o >>= 1) s += __shfl_down_sync(0xffffffffu, s, o);
        if (lane == 0) red[warp][q] = s;
    }
    __syncthreads();
    if (tid < RPB) {
        float s = 0.f;
#pragma unroll
        for (int w = 0; w < 8; w++) s += red[w][tid];
        const float pooled = s + d_b2s;
        const float z = pooled * out_w[0] + out_b[0];
        out[b0 + tid] = 1.f / (1.f + expf(-z));
    }
}

extern "C" void kernel_launch(void* const* d_in, const int* in_sizes, int n_in,
                              void* d_out, int out_size) {
    const float* dense = (const float*)d_in[0];
    const int* sparse = (const int*)d_in[1];
    const float* emb = (const float*)d_in[2];
    const float* W1 = (const float*)d_in[3];
    const float* b1 = (const float*)d_in[4];
    const float* W2 = (const float*)d_in[5];
    const float* b2 = (const float*)d_in[6];
    // d_in[7..10]: attention weights — mathematically dead (softmax over size-1 axis == 1)
    const float* out_w = (const float*)d_in[11];
    const float* out_b = (const float*)d_in[12];
    float* out = (float*)d_out;

    cudaFuncSetAttribute(gemm1_kernel, cudaFuncAttributeMaxDynamicSharedMemorySize, SMEM_GEMM);

    // Launch order keeps gemm1 as launch #4 (the one ncu captures).
    make_pairs_kernel<<<1, 256>>>();
    pack1_kernel<<<TRIP2, 64>>>(W1);
    build_x_kernel<<<BATCH, XS>>>(dense, sparse, emb);
    gemm1_kernel<<<dim3(BATCH / BM, KSPLIT), NTHREADS, SMEM_GEMM>>>();
    w2sum_kernel<<<W2S_BLOCKS + 1, 256>>>(W2, b2);     // independent of gemm1; +1 block sums b2
    final_kernel<<<BATCH / RPB, 256>>>(b1, out_w, out_b, out);
}

// round 17
// speedup vs baseline: 1.2396x; 1.0312x over previous
#include <cuda_runtime.h>
#include <cstdint>
#include <math.h>

// ---------------- problem constants ----------------
#define FDIM 221
#define BATCH 2048
#define XS 224
#define NPAD 256
#define DDIM 13
#define SDIM 26
#define EDIM 8
#define VDIM 100000
#define TRI 24531             // F*(F+1)/2 valid triangle rows
#define TRIP2 24544           // padded K, multiple of 32
#define BKC 32
#define CHUNKS (TRIP2 / BKC)  // 767
#define KSPLIT 9
#define CPS 86                // ceil(767/9)
#define BM 64
#define NTHREADS 288          // 8 consumer warps + 1 producer warp
#define NCONS 256
#define NSTG 4                // pipeline depth (forces 1 CTA/SM via smem)

// ---------------- gemm smem layout (dynamic) ----------------
#define W_STG (BKC * NPAD * 4)          // 32768 B
#define A_STG (BKC * BM * 4)            // 8192 B (plain f32, unduplicated)
#define STG_STRIDE (W_STG + A_STG)      // 40960 B per stage
#define A_OFF W_STG                     // A follows W within a stage
#define SMEM_GEMM (NSTG * STG_STRIDE)   // 163840 B

// ---------------- scratch (device globals; no allocation APIs) ----------------
__device__ float d_X1T[FDIM * BATCH];                  // transposed x: [feature][batch]
__device__ float d_Wp1[(size_t)TRIP2 * NPAD];          // 25.1 MB folded W1
__device__ float d_Yp[(size_t)KSPLIT * BATCH * NPAD];  // 18.9 MB split-K partials
__device__ float d_w2t[TRIP2];                         // folded column-sums of W2
__device__ float d_b2s;
__device__ __align__(16) int d_Tij[TRIP2];             // i | (j<<16)

// ---------------- helpers ----------------
__device__ __forceinline__ uint32_t smem_u32(const void* p) {
    uint32_t a;
    asm("{ .reg .u64 t; cvta.to.shared.u64 t, %1; cvt.u32.u64 %0, t; }" : "=r"(a) : "l"(p));
    return a;
}
__device__ __forceinline__ void cpa16(uint32_t sm, const void* g) {
    asm volatile("cp.async.cg.shared.global [%0], [%1], 16;" :: "r"(sm), "l"(g));
}
__device__ __forceinline__ void fma2(unsigned long long& acc,
                                     unsigned long long a,
                                     unsigned long long b) {
    asm("fma.rn.f32x2 %0, %1, %2, %0;" : "+l"(acc) : "l"(a), "l"(b));
}
__device__ __forceinline__ unsigned long long pack2f(float x) {
    unsigned long long r;
    asm("mov.b64 %0, {%1, %1};" : "=l"(r) : "f"(x));
    return r;
}
__device__ __forceinline__ float2 unpack2f(unsigned long long v) {
    float2 f;
    asm("mov.b64 {%0, %1}, %2;" : "=f"(f.x), "=f"(f.y) : "l"(v));
    return f;
}
__device__ __forceinline__ void mbar_init(uint32_t a, uint32_t c) {
    asm volatile("mbarrier.init.shared.b64 [%0], %1;" :: "r"(a), "r"(c) : "memory");
}
__device__ __forceinline__ void mbar_arrive(uint32_t a) {
    asm volatile("mbarrier.arrive.shared.b64 _, [%0];" :: "r"(a) : "memory");
}
__device__ __forceinline__ void mbar_cp_arrive(uint32_t a) {
    asm volatile("cp.async.mbarrier.arrive.shared::cta.b64 [%0];" :: "r"(a) : "memory");
}
__device__ __forceinline__ void mbar_wait(uint32_t a, uint32_t ph) {
    asm volatile(
        "{\n\t.reg .pred P;\n\t"
        "W_%=:\n\t"
        "mbarrier.try_wait.parity.acquire.cta.shared::cta.b64 P, [%0], %1, 0x989680;\n\t"
        "@P bra.uni D_%=;\n\t"
        "bra.uni W_%=;\n\t"
        "D_%=:\n\t}"
        :: "r"(a), "r"(ph) : "memory");
}

// ---------------- 1) packed triangle index table ----------------
__global__ void make_pairs_kernel() {
    int tid = threadIdx.x;
    for (int i = tid; i < FDIM; i += blockDim.x) {
        int start = i * FDIM - (i * (i - 1)) / 2;
        for (int j = i; j < FDIM; j++)
            d_Tij[start + j - i] = i | (j << 16);
    }
    for (int r = TRI + tid; r < TRIP2; r += blockDim.x) d_Tij[r] = 0;
}

// ---------------- 2) fold W1 -> Wp1[TRIP2][256] ----------------
__global__ void pack1_kernel(const float* __restrict__ W) {
    int r = blockIdx.x;
    float* dst = d_Wp1 + (size_t)r * NPAD;
    if (r >= TRI) {
        for (int c = threadIdx.x; c < NPAD; c += blockDim.x) dst[c] = 0.f;
        return;
    }
    int p = d_Tij[r];
    int i = p & 0xffff, j = p >> 16;
    const float* wa = W + ((size_t)i * FDIM + j) * FDIM;
    const float* wb = W + ((size_t)j * FDIM + i) * FDIM;
    for (int c = threadIdx.x; c < NPAD; c += blockDim.x) {
        float v = 0.f;
        if (c < FDIM) {
            v = wa[c];
            if (i != j) v += wb[c];
        }
        dst[c] = v;
    }
}

// ---------------- 3) fold column-sums of W2 -> w2t; last block also sums b2 ----------------
#define W2S_BLOCKS ((TRIP2 + 7) / 8)
__global__ void w2sum_kernel(const float* __restrict__ W2, const float* __restrict__ b2) {
    if (blockIdx.x == W2S_BLOCKS) {
        __shared__ float red[8];
        int lane = threadIdx.x & 31, warp = threadIdx.x >> 5;
        float s = 0.f;
        for (int f = threadIdx.x; f < FDIM; f += 256) s += b2[f];
#pragma unroll
        for (int o = 16; o > 0; o >>= 1) s += __shfl_down_sync(0xffffffffu, s, o);
        if (lane == 0) red[warp] = s;
        __syncthreads();
        if (threadIdx.x == 0) {
            float t = 0.f;
#pragma unroll
            for (int w = 0; w < 8; w++) t += red[w];
            d_b2s = t;
        }
        return;
    }
    int r = blockIdx.x * 8 + (threadIdx.x >> 5);
    int lane = threadIdx.x & 31;
    if (r >= TRIP2) return;
    float s = 0.f;
    if (r < TRI) {
        int p = d_Tij[r];
        int i = p & 0xffff, j = p >> 16;
        const float* wa = W2 + ((size_t)i * FDIM + j) * FDIM;
        const float* wb = W2 + ((size_t)j * FDIM + i) * FDIM;
        for (int f = lane; f < FDIM; f += 32) {
            s += wa[f];
            if (i != j) s += wb[f];
        }
    }
#pragma unroll
    for (int o = 16; o > 0; o >>= 1) s += __shfl_down_sync(0xffffffffu, s, o);
    if (lane == 0) d_w2t[r] = s;
}

// ---------------- 4) build x transposed: X1T[feature][batch] ----------------
__global__ void build_x_kernel(const float* __restrict__ dense,
                               const int* __restrict__ sparse,
                               const float* __restrict__ emb) {
    int b = blockIdx.x;
    int t = threadIdx.x;
    if (t >= FDIM) return;
    float v;
    if (t < DDIM) {
        v = dense[b * DDIM + t];
    } else {
        int q = t - DDIM;
        int s = q >> 3;
        int e = q & 7;
        int idx = sparse[b * SDIM + s];
        v = emb[((size_t)s * VDIM + idx) * EDIM + e];
    }
    d_X1T[t * BATCH + b] = v;
}

// ---------------- 5) layer-1 interaction GEMM: warp-specialized, 4-stage pipeline, 1 CTA/SM ----------------
__global__ void __launch_bounds__(NTHREADS) gemm1_kernel() {
    extern __shared__ __align__(16) char smem[];
    __shared__ __align__(8) unsigned long long mb[2 * NSTG];   // full[4], empty[4]
    const uint32_t sb = smem_u32(smem);
    const uint32_t mbb = smem_u32(mb);

    const int tid = threadIdx.x;
    const int mBase = blockIdx.x * BM;
    const int split = blockIdx.y;
    const int c0 = split * CPS;
    const int c1 = min(c0 + CPS, CHUNKS);

    if (tid == 0) {
#pragma unroll
        for (int s = 0; s < NSTG; s++) {
            mbar_init(mbb + s * 8, 32);             // full[s]: 32 explicit STS arrivals
            mbar_init(mbb + (NSTG + s) * 8, NCONS); // empty[s]
        }
    }
    __syncthreads();

    if (tid >= NCONS) {
        // ---------------- producer warp ----------------
        const int pl = tid - NCONS;            // 0..31
        const float* xT0 = d_X1T + mBase + pl;
        const float* xT1 = xT0 + 32;
        int s = 0, pe = 1;                     // fresh barriers: first wait per stage passes at parity 1
        for (int ch = c0; ch < c1; ch++) {
            mbar_wait(mbb + (NSTG + s) * 8, (uint32_t)pe);
            // W fill: 2048 x 16B over 32 lanes
            const char* wg = (const char*)d_Wp1 + (size_t)ch * W_STG;
            const uint32_t wsm = sb + s * STG_STRIDE;
#pragma unroll
            for (int q = 0; q < 64; q++) {
                const int off = (pl + 32 * q) * 16;
                cpa16(wsm + off, wg + off);
            }
            mbar_cp_arrive(mbb + s * 8);       // +1 expected now, +1 arrival when copies land
            // A build: 2 m-rows per lane, 32 kk products
            float* Asm = (float*)(smem + s * STG_STRIDE + A_OFF);
            const int rb0 = ch * BKC;
#pragma unroll
            for (int g = 0; g < 4; g++) {
                const int4* t4 = (const int4*)(d_Tij + rb0 + g * 8);
                int4 q0 = __ldg(t4);
                int4 q1 = __ldg(t4 + 1);
                int tj[8] = {q0.x, q0.y, q0.z, q0.w, q1.x, q1.y, q1.z, q1.w};
#pragma unroll
                for (int u = 0; u < 8; u++) {
                    const int i = tj[u] & 0xffff, j = tj[u] >> 16;
                    const float v0 = __ldg(xT0 + (size_t)i * BATCH) * __ldg(xT0 + (size_t)j * BATCH);
                    const float v1 = __ldg(xT1 + (size_t)i * BATCH) * __ldg(xT1 + (size_t)j * BATCH);
                    Asm[(g * 8 + u) * BM + pl] = v0;
                    Asm[(g * 8 + u) * BM + pl + 32] = v1;
                }
            }
            mbar_arrive(mbb + s * 8);          // release: publishes STS
            if (++s == NSTG) { s = 0; pe ^= 1; }
        }
        return;
    }

    // ---------------- consumer warps (tid < 256) ----------------
    const int lane = tid & 31;
    const int wid = tid >> 5;
    const int ml = lane & 3;
    const int nl = lane >> 2;
    const int warpM = wid & 1;
    const int warpN = wid >> 1;

    unsigned long long acc[8][4];
#pragma unroll
    for (int a = 0; a < 8; a++)
#pragma unroll
        for (int s2 = 0; s2 < 4; s2++) acc[a][s2] = 0ULL;

    const int wLaneOff = (warpN * 64 + nl * 4) * 4;
    const int aLaneOff = A_OFF + (warpM * 32 + ml * 8) * 4;

    int s = 0, pf = 0;
    for (int ch = c0; ch < c1; ch++) {
        mbar_wait(mbb + s * 8, (uint32_t)pf);
        const char* Wb = smem + s * STG_STRIDE + wLaneOff;
        const char* Ab = smem + s * STG_STRIDE + aLaneOff;
#pragma unroll 8
        for (int kk = 0; kk < BKC; kk++) {
            const char* Arow = Ab + kk * (BM * 4);
            const char* Wrow = Wb + kk * (NPAD * 4);
            float4 a0 = *reinterpret_cast<const float4*>(Arow);
            float4 a1 = *reinterpret_cast<const float4*>(Arow + 16);
            ulonglong2 w0 = *reinterpret_cast<const ulonglong2*>(Wrow);
            ulonglong2 w1 = *reinterpret_cast<const ulonglong2*>(Wrow + 128);
            unsigned long long wv[4] = {w0.x, w0.y, w1.x, w1.y};
            unsigned long long ad[8];
            ad[0] = pack2f(a0.x); ad[1] = pack2f(a0.y);
            ad[2] = pack2f(a0.z); ad[3] = pack2f(a0.w);
            ad[4] = pack2f(a1.x); ad[5] = pack2f(a1.y);
            ad[6] = pack2f(a1.z); ad[7] = pack2f(a1.w);
#pragma unroll
            for (int g = 0; g < 8; g++)
#pragma unroll
                for (int s2 = 0; s2 < 4; s2++)
                    fma2(acc[g][s2], ad[g], wv[s2]);
        }
        mbar_arrive(mbb + (NSTG + s) * 8);     // release stage back to producer
        if (++s == NSTG) { s = 0; pf ^= 1; }
    }

    // epilogue: deterministic split-K partial store (STG.128, lanes nl-consecutive)
#pragma unroll
    for (int g = 0; g < 8; g++) {
        const int m = mBase + warpM * 32 + ml * 8 + g;
        float* dst = d_Yp + ((size_t)split * BATCH + m) * NPAD + warpN * 64 + nl * 4;
#pragma unroll
        for (int h = 0; h < 2; h++) {
            float2 lo = unpack2f(acc[g][h * 2]);
            float2 hi = unpack2f(acc[g][h * 2 + 1]);
            *reinterpret_cast<float4*>(dst + h * 32) = make_float4(lo.x, lo.y, hi.x, hi.y);
        }
    }
}

// ---------------- 6) fused final: reduce split-K + b1 -> x2 rows; pooled = x2^T S2 x2 + sum(b2); sigmoid ----------------
#define RPB 8
__global__ void final_kernel(const float* __restrict__ b1,
                             const float* __restrict__ out_w,
                             const float* __restrict__ out_b,
                             float* __restrict__ out) {
    __shared__ float xs[RPB][XS];
    __shared__ float red[8][RPB];
    const int tid = threadIdx.x;
    const int b0 = blockIdx.x * RPB;

    // build x2 rows in smem: same arithmetic order as reduce1 (b1 first, then p=0..8)
    for (int idx = tid; idx < RPB * XS; idx += 256) {
        const int r = idx / XS;
        const int c = idx % XS;
        float v = 0.f;
        if (c < FDIM) {
            v = b1[c];
#pragma unroll
            for (int p = 0; p < KSPLIT; p++)
                v += d_Yp[((size_t)p * BATCH + (b0 + r)) * NPAD + c];
        }
        xs[r][c] = v;
    }
    __syncthreads();

    float acc[RPB];
#pragma unroll
    for (int q = 0; q < RPB; q++) acc[q] = 0.f;
    for (int r = tid; r < TRIP2; r += 256) {
        const float w = __ldg(&d_w2t[r]);
        const int p = __ldg(&d_Tij[r]);
        const int i = p & 0xffff, j = p >> 16;
#pragma unroll
        for (int q = 0; q < RPB; q++)
            acc[q] += xs[q][i] * xs[q][j] * w;
    }
    const int lane = tid & 31, warp = tid >> 5;
#pragma unroll
    for (int q = 0; q < RPB; q++) {
        float s = acc[q];
#pragma unroll
        for (int o = 16; o > 0; o >>= 1) s += __shfl_down_sync(0xffffffffu, s, o);
        if (lane == 0) red[warp][q] = s;
    }
    __syncthreads();
    if (tid < RPB) {
        float s = 0.f;
#pragma unroll
        for (int w = 0; w < 8; w++) s += red[w][tid];
        const float pooled = s + d_b2s;
        const float z = pooled * out_w[0] + out_b[0];
        out[b0 + tid] = 1.f / (1.f + expf(-z));
    }
}

extern "C" void kernel_launch(void* const* d_in, const int* in_sizes, int n_in,
                              void* d_out, int out_size) {
    const float* dense = (const float*)d_in[0];
    const int* sparse = (const int*)d_in[1];
    const float* emb = (const float*)d_in[2];
    const float* W1 = (const float*)d_in[3];
    const float* b1 = (const float*)d_in[4];
    const float* W2 = (const float*)d_in[5];
    const float* b2 = (const float*)d_in[6];
    // d_in[7..10]: attention weights — mathematically dead (softmax over size-1 axis == 1)
    const float* out_w = (const float*)d_in[11];
    const float* out_b = (const float*)d_in[12];
    float* out = (float*)d_out;

    cudaFuncSetAttribute(gemm1_kernel, cudaFuncAttributeMaxDynamicSharedMemorySize, SMEM_GEMM);

    // Launch order keeps gemm1 as launch #4 (the one ncu captures).
    make_pairs_kernel<<<1, 256>>>();
    pack1_kernel<<<TRIP2, 64>>>(W1);
    build_x_kernel<<<BATCH, XS>>>(dense, sparse, emb);
    gemm1_kernel<<<dim3(BATCH / BM, KSPLIT), NTHREADS, SMEM_GEMM>>>();
    w2sum_kernel<<<W2S_BLOCKS + 1, 256>>>(W2, b2);     // independent of gemm1; +1 block sums b2
    final_kernel<<<BATCH / RPB, 256>>>(b1, out_w, out_b, out);
}